// round 14
// baseline (speedup 1.0000x reference)
#include <cuda_runtime.h>
#include <cuda_fp16.h>
#include <cstdint>

// Problem constants
#define BB 4
#define TT 1024
#define CC 1024
#define HH 16
#define HS 64
#define LL 12
#define VV 50304
#define NN (BB*TT)          // 4096 tokens
#define FF (4*CC)           // 4096
#define C3 (3*CC)           // 3072
#define NBLM (VV/128)       // 393 LM-head column blocks

// ---------------- scratch (device globals; no allocation allowed) -----------
__device__ float  g_x[NN*CC];
__device__ __half g_h[NN*CC];
__device__ __half g_qkv[(size_t)NN*C3];
__device__ __half g_att[NN*CC];
__device__ __half g_ffh[(size_t)NN*FF];
__device__ float  g_rowloss[NN + 4];
__device__ float2 g_lse[(size_t)NN*NBLM];        // per-tile (max, sumexp) partials
__device__ float  g_logits_fb[(size_t)NN*VV];    // fallback if d_out too small
// transposed weights [N,K] (fp16)
__device__ __half g_WqkvT[(size_t)LL*C3*CC];     // rows: [Wq; Wk; Wv]
__device__ __half g_WoT[(size_t)LL*CC*CC];
__device__ __half g_W1T[(size_t)LL*CC*FF];
__device__ __half g_W2T[(size_t)LL*FF*CC];
__device__ __half g_WlmT[(size_t)CC*VV];

// ---------------- helpers ----------------------------------------------------
__device__ __forceinline__ uint32_t smem_u32(const void* p) {
    uint32_t a;
    asm("{ .reg .u64 t; cvta.to.shared.u64 t, %1; cvt.u32.u64 %0, t; }" : "=r"(a) : "l"(p));
    return a;
}
__device__ __forceinline__ uint32_t swz(uint32_t b) { return b ^ ((b >> 3) & 0x70); }

__device__ __forceinline__ void cp16(void* s, const void* g) {
    uint32_t sa = smem_u32(s);
    asm volatile("cp.async.cg.shared.global [%0], [%1], 16;" :: "r"(sa), "l"(g));
}
#define CP_COMMIT() asm volatile("cp.async.commit_group;" ::: "memory")
#define CP_WAIT(n)  asm volatile("cp.async.wait_group %0;" :: "n"(n) : "memory")

__device__ __forceinline__ void mma_f16(float* d, const uint32_t* a, const uint32_t* b) {
    asm volatile(
        "mma.sync.aligned.m16n8k16.row.col.f32.f16.f16.f32 "
        "{%0,%1,%2,%3}, {%4,%5,%6,%7}, {%8,%9}, {%0,%1,%2,%3};"
        : "+f"(d[0]), "+f"(d[1]), "+f"(d[2]), "+f"(d[3])
        : "r"(a[0]), "r"(a[1]), "r"(a[2]), "r"(a[3]), "r"(b[0]), "r"(b[1]));
}
__device__ __forceinline__ void ldsm_x4_t(uint32_t& r0, uint32_t& r1,
                                          uint32_t& r2, uint32_t& r3, uint32_t addr) {
    asm volatile("ldmatrix.sync.aligned.m8n8.x4.trans.shared.b16 {%0,%1,%2,%3}, [%4];"
        : "=r"(r0), "=r"(r1), "=r"(r2), "=r"(r3) : "r"(addr));
}
__device__ __forceinline__ uint32_t packh2(float a, float b) {
    __half2 h = __floats2half2_rn(a, b);
    return *(uint32_t*)&h;
}

// ---------------- reductions ------------------------------------------------
__device__ __forceinline__ float block_reduce_sum(float v, float* buf) {
    int tid = threadIdx.x;
    buf[tid] = v; __syncthreads();
    for (int s = 128; s > 0; s >>= 1) {
        if (tid < s) buf[tid] += buf[tid + s];
        __syncthreads();
    }
    float r = buf[0]; __syncthreads();
    return r;
}

// ---------------- transpose: dst[N,K] = half(src[K,N]), 64x64 tiles ----------
__global__ __launch_bounds__(256) void transpose_kernel(
    const float* __restrict__ src, __half* __restrict__ dst, int K, int N,
    size_t src_zstride, size_t dst_zstride)
{
    __shared__ float t[64][65];
    const float* s = src + (size_t)blockIdx.z * src_zstride;
    __half* d = dst + (size_t)blockIdx.z * dst_zstride;
    int n0 = blockIdx.x << 6, k0 = blockIdx.y << 6;
    int tid = threadIdx.x;
    int r = tid >> 4, c4 = (tid & 15) << 2;
#pragma unroll
    for (int p = 0; p < 4; p++) {
        float4 v = *(const float4*)(s + (size_t)(k0 + r + p * 16) * N + n0 + c4);
        t[r + p * 16][c4 + 0] = v.x; t[r + p * 16][c4 + 1] = v.y;
        t[r + p * 16][c4 + 2] = v.z; t[r + p * 16][c4 + 3] = v.w;
    }
    __syncthreads();
    int lane = tid & 31, w = tid >> 5;
#pragma unroll
    for (int p = 0; p < 8; p++) {
        int n = w + (p << 3);
        int k = lane << 1;
        *(uint32_t*)(d + (size_t)(n0 + n) * K + k0 + k) =
            packh2(t[k][n], t[k + 1][n]);
    }
}

// ---------------- embedding (float4) -----------------------------------------
__global__ __launch_bounds__(256) void embed_kernel(
    const int* __restrict__ idx, const float* __restrict__ tok,
    const float* __restrict__ pos, float* __restrict__ x)
{
    size_t i4 = (size_t)blockIdx.x * 256 + threadIdx.x;   // over NN*CC/4
    int n = (int)(i4 >> 8);
    int c = (int)(i4 & 255) << 2;
    int t = n & (TT - 1);
    float4 tv = *(const float4*)(tok + (size_t)idx[n] * CC + c);
    float4 pv = *(const float4*)(pos + (size_t)t * CC + c);
    float4 o; o.x = tv.x + pv.x; o.y = tv.y + pv.y; o.z = tv.z + pv.z; o.w = tv.w + pv.w;
    *(float4*)(x + (size_t)n * CC + c) = o;
}

// ---------------- layernorm (warp-shfl reduce, 1 syncthreads) ----------------
__global__ __launch_bounds__(256) void ln_kernel(
    const float* __restrict__ x, const float* __restrict__ g,
    const float* __restrict__ b, __half* __restrict__ out)
{
    __shared__ float ws[8], wss[8];
    int tid = threadIdx.x;
    int row = blockIdx.x;
    int c = tid << 2;
    const float* xr = x + (size_t)row * CC;
    float4 v = *(const float4*)(xr + c);
    float s  = v.x + v.y + v.z + v.w;
    float ss = v.x * v.x + v.y * v.y + v.z * v.z + v.w * v.w;
#pragma unroll
    for (int o = 16; o > 0; o >>= 1) {
        s  += __shfl_down_sync(0xffffffffu, s, o);
        ss += __shfl_down_sync(0xffffffffu, ss, o);
    }
    if ((tid & 31) == 0) { ws[tid >> 5] = s; wss[tid >> 5] = ss; }
    __syncthreads();
    float S = 0.f, SS = 0.f;
#pragma unroll
    for (int i = 0; i < 8; i++) { S += ws[i]; SS += wss[i]; }
    float mu  = S * (1.f / CC);
    float inv = rsqrtf(SS * (1.f / CC) - mu * mu + 1e-5f);
    float4 gv = *(const float4*)(g + c);
    float4 bv = *(const float4*)(b + c);
    uint2 o;
    o.x = packh2((v.x - mu) * inv * gv.x + bv.x, (v.y - mu) * inv * gv.y + bv.y);
    o.y = packh2((v.z - mu) * inv * gv.z + bv.z, (v.w - mu) * inv * gv.w + bv.w);
    *(uint2*)(out + (size_t)row * CC + c) = o;
}

// ---------------- mma.sync fp16 GEMM: C = A[M,K] @ Bt[N,K]^T -----------------
// BM=128, BN=128, BK=64, 256 threads (8 warps, 2x4), 3-stage cp.async pipeline.
// Proven R8/R10 configuration — scalar swizzled LDS fragments. Do NOT cap regs,
// and do NOT add anything to the epilogue while acc is live (R4/R12 lessons).
#define GEMM_SMEM (3*32768)
#define GW 16
__global__ __launch_bounds__(256) void mma_gemm_kernel(
    const __half* __restrict__ A, const __half* __restrict__ Bt,
    const float* __restrict__ bias, const float* __restrict__ res,
    float* __restrict__ C, __half* __restrict__ Ch,
    int M, int N, int K, int relu)
{
    extern __shared__ char smem[];
    int tid = threadIdx.x;
    int wid = tid >> 5, lane = tid & 31;
    int g = lane >> 2, q = lane & 3;
    int wm0 = (wid >> 2) << 6;
    int wn0 = (wid & 3) << 5;

    int Mb = M >> 7, Nb = N >> 7;
    int bid = blockIdx.x;
    int group = bid / (Mb * GW);
    int rem = bid - group * Mb * GW;
    int gw = Nb - group * GW; if (gw > GW) gw = GW;
    int n_blk = group * GW + rem % gw;
    int m_blk = rem / gw;
    int m0 = m_blk << 7, n0 = n_blk << 7;

    const __half* Abase = A + (size_t)m0 * K;
    const __half* Bbase = Bt + (size_t)n0 * K;
    int Kc = K >> 6;

    float acc[4][4][4] = {};

#pragma unroll
    for (int c = 0; c < 2; c++) {
        char* sa = smem + c * 32768;
        char* sbm = sa + 16384;
#pragma unroll
        for (int p = 0; p < 4; p++) {
            int id = p * 256 + tid;
            int row = id >> 3, ch = id & 7;
            uint32_t off = swz((row << 7) + (ch << 4));
            cp16(sa + off, Abase + (size_t)row * K + (c << 6) + (ch << 3));
            cp16(sbm + off, Bbase + (size_t)row * K + (c << 6) + (ch << 3));
        }
        CP_COMMIT();
    }

    for (int c = 0; c < Kc; c++) {
        if (c + 2 < Kc) { CP_WAIT(1); } else { CP_WAIT(0); }
        __syncthreads();
        if (c + 2 < Kc) {
            int cs = c + 2;
            char* sa = smem + (cs % 3) * 32768;
            char* sbm = sa + 16384;
#pragma unroll
            for (int p = 0; p < 4; p++) {
                int id = p * 256 + tid;
                int row = id >> 3, ch = id & 7;
                uint32_t off = swz((row << 7) + (ch << 4));
                cp16(sa + off, Abase + (size_t)row * K + (cs << 6) + (ch << 3));
                cp16(sbm + off, Bbase + (size_t)row * K + (cs << 6) + (ch << 3));
            }
            CP_COMMIT();
        }
        const char* As = smem + (c % 3) * 32768;
        const char* Bs = As + 16384;
#pragma unroll
        for (int ks = 0; ks < 4; ks++) {
            int kb = ks << 5;
            uint32_t af[4][4];
#pragma unroll
            for (int mi = 0; mi < 4; mi++) {
                int r = wm0 + (mi << 4) + g;
                af[mi][0] = *(const uint32_t*)(As + swz((r << 7) + kb + (q << 2)));
                af[mi][1] = *(const uint32_t*)(As + swz(((r + 8) << 7) + kb + (q << 2)));
                af[mi][2] = *(const uint32_t*)(As + swz((r << 7) + kb + 16 + (q << 2)));
                af[mi][3] = *(const uint32_t*)(As + swz(((r + 8) << 7) + kb + 16 + (q << 2)));
            }
            uint32_t bf[4][2];
#pragma unroll
            for (int ni = 0; ni < 4; ni++) {
                int n = wn0 + (ni << 3) + g;
                bf[ni][0] = *(const uint32_t*)(Bs + swz((n << 7) + kb + (q << 2)));
                bf[ni][1] = *(const uint32_t*)(Bs + swz((n << 7) + kb + 16 + (q << 2)));
            }
#pragma unroll
            for (int mi = 0; mi < 4; mi++)
#pragma unroll
                for (int ni = 0; ni < 4; ni++)
                    mma_f16(acc[mi][ni], af[mi], bf[ni]);
        }
    }

#pragma unroll
    for (int mi = 0; mi < 4; mi++) {
#pragma unroll
        for (int half = 0; half < 2; half++) {
            int row = m0 + wm0 + (mi << 4) + g + half * 8;
            const float* rrow = res ? res + (size_t)row * N : nullptr;
#pragma unroll
            for (int ni = 0; ni < 4; ni++) {
                int col = n0 + wn0 + (ni << 3) + (q << 1);
                float v0 = acc[mi][ni][half * 2 + 0];
                float v1 = acc[mi][ni][half * 2 + 1];
                if (bias) { v0 += bias[col]; v1 += bias[col + 1]; }
                if (relu) { v0 = fmaxf(v0, 0.f); v1 = fmaxf(v1, 0.f); }
                if (rrow) { v0 += rrow[col]; v1 += rrow[col + 1]; }
                if (Ch) {
                    *(uint32_t*)(Ch + (size_t)row * N + col) = packh2(v0, v1);
                } else {
                    float2 o; o.x = v0; o.y = v1;
                    *(float2*)(C + (size_t)row * N + col) = o;
                }
            }
        }
    }
}

// ---------------- LM-head GEMM clone with fused LSE partials -----------------
// Mainloop identical to mma_gemm_kernel. Epilogue: SINGLE pass over acc (same
// register liveness as the plain kernel) that writes C and stages the tile
// into padded smem; then a smem-only phase computes per-row (max, sumexp).
__global__ __launch_bounds__(256) void mma_gemm_lse_kernel(
    const __half* __restrict__ A, const __half* __restrict__ Bt,
    const float* __restrict__ bias,
    float* __restrict__ C, float2* __restrict__ lse,
    int M, int N, int K)
{
    extern __shared__ char smem[];
    int tid = threadIdx.x;
    int wid = tid >> 5, lane = tid & 31;
    int g = lane >> 2, q = lane & 3;
    int wm0 = (wid >> 2) << 6;
    int wn0 = (wid & 3) << 5;

    int Mb = M >> 7, Nb = N >> 7;
    int bid = blockIdx.x;
    int group = bid / (Mb * GW);
    int rem = bid - group * Mb * GW;
    int gw = Nb - group * GW; if (gw > GW) gw = GW;
    int n_blk = group * GW + rem % gw;
    int m_blk = rem / gw;
    int m0 = m_blk << 7, n0 = n_blk << 7;

    const __half* Abase = A + (size_t)m0 * K;
    const __half* Bbase = Bt + (size_t)n0 * K;
    int Kc = K >> 6;

    float acc[4][4][4] = {};

#pragma unroll
    for (int c = 0; c < 2; c++) {
        char* sa = smem + c * 32768;
        char* sbm = sa + 16384;
#pragma unroll
        for (int p = 0; p < 4; p++) {
            int id = p * 256 + tid;
            int row = id >> 3, ch = id & 7;
            uint32_t off = swz((row << 7) + (ch << 4));
            cp16(sa + off, Abase + (size_t)row * K + (c << 6) + (ch << 3));
            cp16(sbm + off, Bbase + (size_t)row * K + (c << 6) + (ch << 3));
        }
        CP_COMMIT();
    }

    for (int c = 0; c < Kc; c++) {
        if (c + 2 < Kc) { CP_WAIT(1); } else { CP_WAIT(0); }
        __syncthreads();
        if (c + 2 < Kc) {
            int cs = c + 2;
            char* sa = smem + (cs % 3) * 32768;
            char* sbm = sa + 16384;
#pragma unroll
            for (int p = 0; p < 4; p++) {
                int id = p * 256 + tid;
                int row = id >> 3, ch = id & 7;
                uint32_t off = swz((row << 7) + (ch << 4));
                cp16(sa + off, Abase + (size_t)row * K + (cs << 6) + (ch << 3));
                cp16(sbm + off, Bbase + (size_t)row * K + (cs << 6) + (ch << 3));
            }
            CP_COMMIT();
        }
        const char* As = smem + (c % 3) * 32768;
        const char* Bs = As + 16384;
#pragma unroll
        for (int ks = 0; ks < 4; ks++) {
            int kb = ks << 5;
            uint32_t af[4][4];
#pragma unroll
            for (int mi = 0; mi < 4; mi++) {
                int r = wm0 + (mi << 4) + g;
                af[mi][0] = *(const uint32_t*)(As + swz((r << 7) + kb + (q << 2)));
                af[mi][1] = *(const uint32_t*)(As + swz(((r + 8) << 7) + kb + (q << 2)));
                af[mi][2] = *(const uint32_t*)(As + swz((r << 7) + kb + 16 + (q << 2)));
                af[mi][3] = *(const uint32_t*)(As + swz(((r + 8) << 7) + kb + 16 + (q << 2)));
            }
            uint32_t bf[4][2];
#pragma unroll
            for (int ni = 0; ni < 4; ni++) {
                int n = wn0 + (ni << 3) + g;
                bf[ni][0] = *(const uint32_t*)(Bs + swz((n << 7) + kb + (q << 2)));
                bf[ni][1] = *(const uint32_t*)(Bs + swz((n << 7) + kb + 16 + (q << 2)));
            }
#pragma unroll
            for (int mi = 0; mi < 4; mi++)
#pragma unroll
                for (int ni = 0; ni < 4; ni++)
                    mma_f16(acc[mi][ni], af[mi], bf[ni]);
        }
    }

    __syncthreads();                  // pipeline drained; smem reusable
    float* tile = (float*)smem;       // [128][129] padded fp32 tile (66 KB)

    // single pass: write C + stage smem (acc dies progressively, like R10)
#pragma unroll
    for (int mi = 0; mi < 4; mi++) {
#pragma unroll
        for (int half = 0; half < 2; half++) {
            int rl = wm0 + (mi << 4) + g + half * 8;
            int row = m0 + rl;
#pragma unroll
            for (int ni = 0; ni < 4; ni++) {
                int lcol = wn0 + (ni << 3) + (q << 1);
                int col = n0 + lcol;
                float v0 = acc[mi][ni][half * 2 + 0] + bias[col];
                float v1 = acc[mi][ni][half * 2 + 1] + bias[col + 1];
                float2 o; o.x = v0; o.y = v1;
                *(float2*)(C + (size_t)row * N + col) = o;
                tile[rl * 129 + lcol]     = v0;
                tile[rl * 129 + lcol + 1] = v1;
            }
        }
    }
    __syncthreads();
    // smem-only phase: thread t scans row t (conflict-free via 129 padding)
    if (tid < 128) {
        const float* tr = tile + tid * 129;
        float mx = tr[0];
#pragma unroll 8
        for (int j = 1; j < 128; j++) mx = fmaxf(mx, tr[j]);
        float sm = 0.f;
#pragma unroll 8
        for (int j = 0; j < 128; j++) sm += __expf(tr[j] - mx);
        float2 o; o.x = mx; o.y = sm;
        lse[(size_t)(m0 + tid) * NBLM + n_blk] = o;
    }
}

// ---------------- fused flash attention --------------------------------------
__global__ __launch_bounds__(128) void flash_attn(
    const __half* __restrict__ qkv, __half* __restrict__ o)
{
    __shared__ __align__(16) __half Qs[64 * 64];
    __shared__ __align__(16) __half Ks[2][64 * 64];
    __shared__ __align__(16) __half Vs[2][64 * 64];

    int it = (int)gridDim.x - 1 - (int)blockIdx.x;   // longest tiles first
    int bh = blockIdx.y;
    int b = bh >> 4, h = bh & 15;
    int tid = threadIdx.x;
    int wid = tid >> 5, lane = tid & 31;
    int g = lane >> 2, q = lane & 3;
    int wr = wid << 4;

    const __half* Qg = qkv + ((size_t)b * TT + (size_t)it * 64) * C3 + h * 64;

#pragma unroll
    for (int p = 0; p < 4; p++) {
        int id = p * 128 + tid;
        int row = id >> 3, ch = id & 7;
        cp16((char*)Qs + swz((row << 7) + (ch << 4)), Qg + (size_t)row * C3 + (ch << 3));
    }
    CP_COMMIT();

    {
        const __half* Kg = qkv + (size_t)b * TT * C3 + CC + h * 64;
        const __half* Vg = qkv + (size_t)b * TT * C3 + 2 * CC + h * 64;
#pragma unroll
        for (int p = 0; p < 4; p++) {
            int id = p * 128 + tid;
            int row = id >> 3, ch = id & 7;
            uint32_t off = swz((row << 7) + (ch << 4));
            cp16((char*)Ks[0] + off, Kg + (size_t)row * C3 + (ch << 3));
            cp16((char*)Vs[0] + off, Vg + (size_t)row * C3 + (ch << 3));
        }
        CP_COMMIT();
    }

    float m0 = -1e30f, m1 = -1e30f;
    float l0 = 0.f, l1 = 0.f;
    float oacc[8][4] = {};

    for (int jt = 0; jt <= it; jt++) {
        int buf = jt & 1;
        if (jt < it) {
            int nb = (jt + 1) & 1;
            const __half* Kg = qkv + ((size_t)b * TT + (size_t)(jt + 1) * 64) * C3 + CC + h * 64;
            const __half* Vg = qkv + ((size_t)b * TT + (size_t)(jt + 1) * 64) * C3 + 2 * CC + h * 64;
#pragma unroll
            for (int p = 0; p < 4; p++) {
                int id = p * 128 + tid;
                int row = id >> 3, ch = id & 7;
                uint32_t off = swz((row << 7) + (ch << 4));
                cp16((char*)Ks[nb] + off, Kg + (size_t)row * C3 + (ch << 3));
                cp16((char*)Vs[nb] + off, Vg + (size_t)row * C3 + (ch << 3));
            }
            CP_COMMIT();
            CP_WAIT(1);
        } else {
            CP_WAIT(0);
        }
        __syncthreads();

        float sacc[8][4] = {};
        const char* Qb = (const char*)Qs;
        const char* Kb = (const char*)Ks[buf];
#pragma unroll
        for (int ks = 0; ks < 4; ks++) {
            int kb = ks << 5;
            uint32_t af[4];
            af[0] = *(const uint32_t*)(Qb + swz(((wr + g) << 7) + kb + (q << 2)));
            af[1] = *(const uint32_t*)(Qb + swz(((wr + g + 8) << 7) + kb + (q << 2)));
            af[2] = *(const uint32_t*)(Qb + swz(((wr + g) << 7) + kb + 16 + (q << 2)));
            af[3] = *(const uint32_t*)(Qb + swz(((wr + g + 8) << 7) + kb + 16 + (q << 2)));
#pragma unroll
            for (int nt = 0; nt < 8; nt++) {
                uint32_t bf[2];
                bf[0] = *(const uint32_t*)(Kb + swz((((nt << 3) + g) << 7) + kb + (q << 2)));
                bf[1] = *(const uint32_t*)(Kb + swz((((nt << 3) + g) << 7) + kb + 16 + (q << 2)));
                mma_f16(sacc[nt], af, bf);
            }
        }

        bool diag = (jt == it);
        float mn0 = -1e30f, mn1 = -1e30f;
#pragma unroll
        for (int nt = 0; nt < 8; nt++) {
#pragma unroll
            for (int j = 0; j < 4; j++) {
                float s = sacc[nt][j] * 0.125f;
                if (diag) {
                    int col = (nt << 3) + (q << 1) + (j & 1);
                    int row = wr + g + ((j >> 1) << 3);
                    if (col > row) s = -1e30f;
                }
                sacc[nt][j] = s;
            }
            mn0 = fmaxf(mn0, fmaxf(sacc[nt][0], sacc[nt][1]));
            mn1 = fmaxf(mn1, fmaxf(sacc[nt][2], sacc[nt][3]));
        }
        mn0 = fmaxf(mn0, __shfl_xor_sync(0xffffffffu, mn0, 1));
        mn0 = fmaxf(mn0, __shfl_xor_sync(0xffffffffu, mn0, 2));
        mn1 = fmaxf(mn1, __shfl_xor_sync(0xffffffffu, mn1, 1));
        mn1 = fmaxf(mn1, __shfl_xor_sync(0xffffffffu, mn1, 2));

        float mnew0 = fmaxf(m0, mn0), mnew1 = fmaxf(m1, mn1);
        float a0 = __expf(m0 - mnew0), a1 = __expf(m1 - mnew1);
        m0 = mnew0; m1 = mnew1;

        float rs0 = 0.f, rs1 = 0.f;
        uint32_t ph[8][2];
#pragma unroll
        for (int nt = 0; nt < 8; nt++) {
            float p0 = __expf(sacc[nt][0] - m0);
            float p1 = __expf(sacc[nt][1] - m0);
            float p2 = __expf(sacc[nt][2] - m1);
            float p3 = __expf(sacc[nt][3] - m1);
            rs0 += p0 + p1; rs1 += p2 + p3;
            ph[nt][0] = packh2(p0, p1);
            ph[nt][1] = packh2(p2, p3);
        }
        rs0 += __shfl_xor_sync(0xffffffffu, rs0, 1);
        rs0 += __shfl_xor_sync(0xffffffffu, rs0, 2);
        rs1 += __shfl_xor_sync(0xffffffffu, rs1, 1);
        rs1 += __shfl_xor_sync(0xffffffffu, rs1, 2);
        l0 = l0 * a0 + rs0;
        l1 = l1 * a1 + rs1;
#pragma unroll
        for (int nt = 0; nt < 8; nt++) {
            oacc[nt][0] *= a0; oacc[nt][1] *= a0;
            oacc[nt][2] *= a1; oacc[nt][3] *= a1;
        }

        uint32_t vbase = smem_u32(Vs[buf]);
        int t = lane >> 3, r = lane & 7;
#pragma unroll
        for (int s = 0; s < 4; s++) {
            uint32_t pa[4] = { ph[2 * s][0], ph[2 * s][1], ph[2 * s + 1][0], ph[2 * s + 1][1] };
#pragma unroll
            for (int ntp = 0; ntp < 4; ntp++) {
                uint32_t b0, b1, b2, b3;
                uint32_t la = vbase + swz((((s << 4) + ((t & 1) << 3) + r) << 7) +
                                          (((ntp << 1) + (t >> 1)) << 4));
                ldsm_x4_t(b0, b1, b2, b3, la);
                uint32_t bA[2] = { b0, b1 }, bB[2] = { b2, b3 };
                mma_f16(oacc[2 * ntp], pa, bA);
                mma_f16(oacc[2 * ntp + 1], pa, bB);
            }
        }
        __syncthreads();
    }

    float i0 = 1.f / l0, i1 = 1.f / l1;
    int rowg = b * TT + it * 64 + wr + g;
    __half* O0 = o + (size_t)rowg * CC + h * 64;
    __half* O1 = o + (size_t)(rowg + 8) * CC + h * 64;
#pragma unroll
    for (int nt = 0; nt < 8; nt++) {
        int col = (nt << 3) + (q << 1);
        *(uint32_t*)(O0 + col) = packh2(oacc[nt][0] * i0, oacc[nt][1] * i0);
        *(uint32_t*)(O1 + col) = packh2(oacc[nt][2] * i1, oacc[nt][3] * i1);
    }
}

// ---------------- loss finalize: merge LSE partials, gather target logit -----
__global__ __launch_bounds__(128) void lse_loss_kernel(
    const float* __restrict__ logits, const float2* __restrict__ lse,
    const int* __restrict__ targets, float* __restrict__ rl)
{
    __shared__ float bm[128], bs[128];
    int row = blockIdx.x;
    int tid = threadIdx.x;
    const float2* lrow = lse + (size_t)row * NBLM;
    float m = -3.4e38f, s = 0.f;
    for (int j = tid; j < NBLM; j += 128) {
        float2 p = lrow[j];
        float nm = fmaxf(m, p.x);
        s = s * __expf(m - nm) + p.y * __expf(p.x - nm);
        m = nm;
    }
    bm[tid] = m; bs[tid] = s;
    __syncthreads();
    for (int st = 64; st > 0; st >>= 1) {
        if (tid < st) {
            float m2 = bm[tid + st], s2 = bs[tid + st];
            float nm = fmaxf(bm[tid], m2);
            bs[tid] = bs[tid] * __expf(bm[tid] - nm) + s2 * __expf(m2 - nm);
            bm[tid] = nm;
        }
        __syncthreads();
    }
    if (tid == 0) {
        int t = targets[row];
        rl[row] = -(logits[(size_t)row * VV + t] - bm[0] - logf(bs[0]));
    }
}

__global__ __launch_bounds__(256) void loss_reduce_kernel(
    const float* __restrict__ rl, float* __restrict__ out)
{
    __shared__ float buf[256];
    float s = 0.f;
    for (int i = threadIdx.x; i < NN; i += 256) s += rl[i];
    s = block_reduce_sum(s, buf);
    if (threadIdx.x == 0) out[0] = s * (1.f / NN);
}

// ---------------- host orchestration ----------------------------------------
static inline void run_gemm(const __half* A, const __half* Wt, const float* bias,
                            const float* res, float* C, __half* Ch,
                            int M, int N, int K, int relu)
{
    int grid = (M / 128) * (N / 128);
    mma_gemm_kernel<<<grid, 256, GEMM_SMEM>>>(A, Wt, bias, res, C, Ch, M, N, K, relu);
}

extern "C" void kernel_launch(void* const* d_in, const int* in_sizes, int n_in,
                              void* d_out, int out_size)
{
    const int*   idx     = (const int*)  d_in[0];
    const int*   targets = (const int*)  d_in[1];
    const float* tok     = (const float*)d_in[2];
    const float* pos     = (const float*)d_in[3];
    const float* ln1_g   = (const float*)d_in[4];
    const float* ln1_b   = (const float*)d_in[5];
    const float* Wq      = (const float*)d_in[6];
    const float* Wk      = (const float*)d_in[7];
    const float* Wv      = (const float*)d_in[8];
    const float* Wo      = (const float*)d_in[9];
    const float* bo      = (const float*)d_in[10];
    const float* ln2_g   = (const float*)d_in[11];
    const float* ln2_b   = (const float*)d_in[12];
    const float* W1      = (const float*)d_in[13];
    const float* b1      = (const float*)d_in[14];
    const float* W2      = (const float*)d_in[15];
    const float* b2      = (const float*)d_in[16];
    const float* lnf_g   = (const float*)d_in[17];
    const float* lnf_b   = (const float*)d_in[18];
    const float* Wlm     = (const float*)d_in[19];
    const float* blm     = (const float*)d_in[20];
    (void)in_sizes; (void)n_in;

    cudaFuncSetAttribute(mma_gemm_kernel,
                         cudaFuncAttributeMaxDynamicSharedMemorySize, GEMM_SMEM);
    cudaFuncSetAttribute(mma_gemm_lse_kernel,
                         cudaFuncAttributeMaxDynamicSharedMemorySize, GEMM_SMEM);

    void* p;
    cudaGetSymbolAddress(&p, g_x);      float*  x    = (float*)p;
    cudaGetSymbolAddress(&p, g_h);      __half* h    = (__half*)p;
    cudaGetSymbolAddress(&p, g_qkv);    __half* qkv  = (__half*)p;
    cudaGetSymbolAddress(&p, g_att);    __half* att  = (__half*)p;
    cudaGetSymbolAddress(&p, g_ffh);    __half* ffh  = (__half*)p;
    cudaGetSymbolAddress(&p, g_rowloss);float*  rl   = (float*)p;
    cudaGetSymbolAddress(&p, g_lse);    float2* lse  = (float2*)p;
    cudaGetSymbolAddress(&p, g_logits_fb); float* logits_fb = (float*)p;
    cudaGetSymbolAddress(&p, g_WqkvT);  __half* WqkvT = (__half*)p;
    cudaGetSymbolAddress(&p, g_WoT);    __half* WoT  = (__half*)p;
    cudaGetSymbolAddress(&p, g_W1T);    __half* W1T  = (__half*)p;
    cudaGetSymbolAddress(&p, g_W2T);    __half* W2T  = (__half*)p;
    cudaGetSymbolAddress(&p, g_WlmT);   __half* WlmT = (__half*)p;

    const size_t NV = (size_t)NN * VV;
    float* out = (float*)d_out;
    bool big = ((size_t)out_size >= NV);
    float* logits   = big ? out : logits_fb;
    float* loss_dst = ((size_t)out_size > NV) ? out + NV
                    : (big ? rl + NN : out);

    // transpose all weights to fp16 [N,K]; QKV packed as [3C,K] (64x64 tiles)
    transpose_kernel<<<dim3(CC/64, CC/64, LL), 256>>>(Wq, WqkvT + 0 * (size_t)CC * CC,
        CC, CC, (size_t)CC * CC, (size_t)C3 * CC);
    transpose_kernel<<<dim3(CC/64, CC/64, LL), 256>>>(Wk, WqkvT + 1 * (size_t)CC * CC,
        CC, CC, (size_t)CC * CC, (size_t)C3 * CC);
    transpose_kernel<<<dim3(CC/64, CC/64, LL), 256>>>(Wv, WqkvT + 2 * (size_t)CC * CC,
        CC, CC, (size_t)CC * CC, (size_t)C3 * CC);
    transpose_kernel<<<dim3(CC/64, CC/64, LL), 256>>>(Wo, WoT, CC, CC,
        (size_t)CC * CC, (size_t)CC * CC);
    transpose_kernel<<<dim3(FF/64, CC/64, LL), 256>>>(W1, W1T, CC, FF,
        (size_t)CC * FF, (size_t)CC * FF);
    transpose_kernel<<<dim3(CC/64, FF/64, LL), 256>>>(W2, W2T, FF, CC,
        (size_t)FF * CC, (size_t)FF * CC);
    transpose_kernel<<<dim3(VV/64, CC/64, 1),  256>>>(Wlm, WlmT, CC, VV, 0, 0);

    // embedding
    embed_kernel<<<(NN * CC / 4) / 256, 256>>>(idx, tok, pos, x);

    for (int l = 0; l < LL; l++) {
        const size_t oC  = (size_t)l * CC;
        const size_t oCC = (size_t)l * CC * CC;
        const size_t oCF = (size_t)l * CC * FF;
        const size_t oF  = (size_t)l * FF;
        const size_t oQ  = (size_t)l * C3 * CC;

        ln_kernel<<<NN, 256>>>(x, ln1_g + oC, ln1_b + oC, h);
        run_gemm(h, WqkvT + oQ, nullptr, nullptr, nullptr, qkv, NN, C3, CC, 0);

        flash_attn<<<dim3(TT / 64, BB * HH), 128>>>(qkv, att);

        run_gemm(att, WoT + oCC, bo + oC, x, x, nullptr, NN, CC, CC, 0);

        ln_kernel<<<NN, 256>>>(x, ln2_g + oC, ln2_b + oC, h);
        run_gemm(h, W1T + oCF, b1 + oF, nullptr, nullptr, ffh, NN, FF, CC, 1);
        run_gemm(ffh, W2T + oCF, b2 + oC, x, x, nullptr, NN, CC, FF, 0);
    }

    ln_kernel<<<NN, 256>>>(x, lnf_g, lnf_b, h);
    // LM head with fused per-tile logsumexp partials (dedicated clone kernel)
    {
        int grid = (NN / 128) * (VV / 128);
        mma_gemm_lse_kernel<<<grid, 256, GEMM_SMEM>>>(h, WlmT, blm, logits, lse,
                                                      NN, VV, CC);
    }

    lse_loss_kernel<<<NN, 128>>>(logits, lse, targets, rl);
    loss_reduce_kernel<<<1, 256>>>(rl, loss_dst);
}

// round 15
// speedup vs baseline: 1.0328x; 1.0328x over previous
#include <cuda_runtime.h>
#include <cuda_fp16.h>
#include <cstdint>

// Problem constants
#define BB 4
#define TT 1024
#define CC 1024
#define HH 16
#define HS 64
#define LL 12
#define VV 50304
#define NN (BB*TT)          // 4096 tokens
#define FF (4*CC)           // 4096
#define C3 (3*CC)           // 3072
#define NSPL 4              // row_loss vocab splits
#define VCH (VV/NSPL)       // 12576 (= 3144 float4)

// ---------------- scratch (device globals; no allocation allowed) -----------
__device__ float  g_x[NN*CC];
__device__ __half g_h[NN*CC];
__device__ __half g_qkv[(size_t)NN*C3];
__device__ __half g_att[NN*CC];
__device__ __half g_ffh[(size_t)NN*FF];
__device__ float  g_rowloss[NN + 4];
__device__ float2 g_lsep[(size_t)NN*NSPL];       // per-chunk (max, sumexp) partials
__device__ float  g_logits_fb[(size_t)NN*VV];    // fallback if d_out too small
// transposed weights [N,K] (fp16)
__device__ __half g_WqkvT[(size_t)LL*C3*CC];     // rows: [Wq; Wk; Wv]
__device__ __half g_WoT[(size_t)LL*CC*CC];
__device__ __half g_W1T[(size_t)LL*CC*FF];
__device__ __half g_W2T[(size_t)LL*FF*CC];
__device__ __half g_WlmT[(size_t)CC*VV];

// ---------------- helpers ----------------------------------------------------
__device__ __forceinline__ uint32_t smem_u32(const void* p) {
    uint32_t a;
    asm("{ .reg .u64 t; cvta.to.shared.u64 t, %1; cvt.u32.u64 %0, t; }" : "=r"(a) : "l"(p));
    return a;
}
__device__ __forceinline__ uint32_t swz(uint32_t b) { return b ^ ((b >> 3) & 0x70); }

__device__ __forceinline__ void cp16(void* s, const void* g) {
    uint32_t sa = smem_u32(s);
    asm volatile("cp.async.cg.shared.global [%0], [%1], 16;" :: "r"(sa), "l"(g));
}
#define CP_COMMIT() asm volatile("cp.async.commit_group;" ::: "memory")
#define CP_WAIT(n)  asm volatile("cp.async.wait_group %0;" :: "n"(n) : "memory")

__device__ __forceinline__ void mma_f16(float* d, const uint32_t* a, const uint32_t* b) {
    asm volatile(
        "mma.sync.aligned.m16n8k16.row.col.f32.f16.f16.f32 "
        "{%0,%1,%2,%3}, {%4,%5,%6,%7}, {%8,%9}, {%0,%1,%2,%3};"
        : "+f"(d[0]), "+f"(d[1]), "+f"(d[2]), "+f"(d[3])
        : "r"(a[0]), "r"(a[1]), "r"(a[2]), "r"(a[3]), "r"(b[0]), "r"(b[1]));
}
__device__ __forceinline__ void ldsm_x4_t(uint32_t& r0, uint32_t& r1,
                                          uint32_t& r2, uint32_t& r3, uint32_t addr) {
    asm volatile("ldmatrix.sync.aligned.m8n8.x4.trans.shared.b16 {%0,%1,%2,%3}, [%4];"
        : "=r"(r0), "=r"(r1), "=r"(r2), "=r"(r3) : "r"(addr));
}
__device__ __forceinline__ uint32_t packh2(float a, float b) {
    __half2 h = __floats2half2_rn(a, b);
    return *(uint32_t*)&h;
}

// ---------------- reductions ------------------------------------------------
__device__ __forceinline__ float block_reduce_sum(float v, float* buf) {
    int tid = threadIdx.x;
    buf[tid] = v; __syncthreads();
    for (int s = 128; s > 0; s >>= 1) {
        if (tid < s) buf[tid] += buf[tid + s];
        __syncthreads();
    }
    float r = buf[0]; __syncthreads();
    return r;
}
__device__ __forceinline__ float block_reduce_max(float v, float* buf) {
    int tid = threadIdx.x;
    buf[tid] = v; __syncthreads();
    for (int s = 128; s > 0; s >>= 1) {
        if (tid < s) buf[tid] = fmaxf(buf[tid], buf[tid + s]);
        __syncthreads();
    }
    float r = buf[0]; __syncthreads();
    return r;
}

// ---------------- transpose: dst[N,K] = half(src[K,N]), 64x64 tiles ----------
__global__ __launch_bounds__(256) void transpose_kernel(
    const float* __restrict__ src, __half* __restrict__ dst, int K, int N,
    size_t src_zstride, size_t dst_zstride)
{
    __shared__ float t[64][65];
    const float* s = src + (size_t)blockIdx.z * src_zstride;
    __half* d = dst + (size_t)blockIdx.z * dst_zstride;
    int n0 = blockIdx.x << 6, k0 = blockIdx.y << 6;
    int tid = threadIdx.x;
    int r = tid >> 4, c4 = (tid & 15) << 2;
#pragma unroll
    for (int p = 0; p < 4; p++) {
        float4 v = *(const float4*)(s + (size_t)(k0 + r + p * 16) * N + n0 + c4);
        t[r + p * 16][c4 + 0] = v.x; t[r + p * 16][c4 + 1] = v.y;
        t[r + p * 16][c4 + 2] = v.z; t[r + p * 16][c4 + 3] = v.w;
    }
    __syncthreads();
    int lane = tid & 31, w = tid >> 5;
#pragma unroll
    for (int p = 0; p < 8; p++) {
        int n = w + (p << 3);
        int k = lane << 1;
        *(uint32_t*)(d + (size_t)(n0 + n) * K + k0 + k) =
            packh2(t[k][n], t[k + 1][n]);
    }
}

// ---------------- embedding (float4) -----------------------------------------
__global__ __launch_bounds__(256) void embed_kernel(
    const int* __restrict__ idx, const float* __restrict__ tok,
    const float* __restrict__ pos, float* __restrict__ x)
{
    size_t i4 = (size_t)blockIdx.x * 256 + threadIdx.x;   // over NN*CC/4
    int n = (int)(i4 >> 8);
    int c = (int)(i4 & 255) << 2;
    int t = n & (TT - 1);
    float4 tv = *(const float4*)(tok + (size_t)idx[n] * CC + c);
    float4 pv = *(const float4*)(pos + (size_t)t * CC + c);
    float4 o; o.x = tv.x + pv.x; o.y = tv.y + pv.y; o.z = tv.z + pv.z; o.w = tv.w + pv.w;
    *(float4*)(x + (size_t)n * CC + c) = o;
}

// ---------------- layernorm (warp-shfl reduce, 1 syncthreads) ----------------
__global__ __launch_bounds__(256) void ln_kernel(
    const float* __restrict__ x, const float* __restrict__ g,
    const float* __restrict__ b, __half* __restrict__ out)
{
    __shared__ float ws[8], wss[8];
    int tid = threadIdx.x;
    int row = blockIdx.x;
    int c = tid << 2;
    const float* xr = x + (size_t)row * CC;
    float4 v = *(const float4*)(xr + c);
    float s  = v.x + v.y + v.z + v.w;
    float ss = v.x * v.x + v.y * v.y + v.z * v.z + v.w * v.w;
#pragma unroll
    for (int o = 16; o > 0; o >>= 1) {
        s  += __shfl_down_sync(0xffffffffu, s, o);
        ss += __shfl_down_sync(0xffffffffu, ss, o);
    }
    if ((tid & 31) == 0) { ws[tid >> 5] = s; wss[tid >> 5] = ss; }
    __syncthreads();
    float S = 0.f, SS = 0.f;
#pragma unroll
    for (int i = 0; i < 8; i++) { S += ws[i]; SS += wss[i]; }
    float mu  = S * (1.f / CC);
    float inv = rsqrtf(SS * (1.f / CC) - mu * mu + 1e-5f);
    float4 gv = *(const float4*)(g + c);
    float4 bv = *(const float4*)(b + c);
    uint2 o;
    o.x = packh2((v.x - mu) * inv * gv.x + bv.x, (v.y - mu) * inv * gv.y + bv.y);
    o.y = packh2((v.z - mu) * inv * gv.z + bv.z, (v.w - mu) * inv * gv.w + bv.w);
    *(uint2*)(out + (size_t)row * CC + c) = o;
}

// ---------------- mma.sync fp16 GEMM: C = A[M,K] @ Bt[N,K]^T -----------------
// BM=128, BN=128, BK=64, 256 threads (8 warps, 2x4), 3-stage cp.async pipeline.
// Proven R8/R10 configuration — scalar swizzled LDS fragments. Do NOT cap regs,
// do NOT touch the epilogue while acc is live, do NOT fuse reductions here
// (R4/R12/R14 lessons — this kernel is at its register ceiling).
#define GEMM_SMEM (3*32768)
#define GW 16
__global__ __launch_bounds__(256) void mma_gemm_kernel(
    const __half* __restrict__ A, const __half* __restrict__ Bt,
    const float* __restrict__ bias, const float* __restrict__ res,
    float* __restrict__ C, __half* __restrict__ Ch,
    int M, int N, int K, int relu)
{
    extern __shared__ char smem[];
    int tid = threadIdx.x;
    int wid = tid >> 5, lane = tid & 31;
    int g = lane >> 2, q = lane & 3;
    int wm0 = (wid >> 2) << 6;
    int wn0 = (wid & 3) << 5;

    int Mb = M >> 7, Nb = N >> 7;
    int bid = blockIdx.x;
    int group = bid / (Mb * GW);
    int rem = bid - group * Mb * GW;
    int gw = Nb - group * GW; if (gw > GW) gw = GW;
    int n_blk = group * GW + rem % gw;
    int m_blk = rem / gw;
    int m0 = m_blk << 7, n0 = n_blk << 7;

    const __half* Abase = A + (size_t)m0 * K;
    const __half* Bbase = Bt + (size_t)n0 * K;
    int Kc = K >> 6;

    float acc[4][4][4] = {};

#pragma unroll
    for (int c = 0; c < 2; c++) {
        char* sa = smem + c * 32768;
        char* sbm = sa + 16384;
#pragma unroll
        for (int p = 0; p < 4; p++) {
            int id = p * 256 + tid;
            int row = id >> 3, ch = id & 7;
            uint32_t off = swz((row << 7) + (ch << 4));
            cp16(sa + off, Abase + (size_t)row * K + (c << 6) + (ch << 3));
            cp16(sbm + off, Bbase + (size_t)row * K + (c << 6) + (ch << 3));
        }
        CP_COMMIT();
    }

    for (int c = 0; c < Kc; c++) {
        if (c + 2 < Kc) { CP_WAIT(1); } else { CP_WAIT(0); }
        __syncthreads();
        if (c + 2 < Kc) {
            int cs = c + 2;
            char* sa = smem + (cs % 3) * 32768;
            char* sbm = sa + 16384;
#pragma unroll
            for (int p = 0; p < 4; p++) {
                int id = p * 256 + tid;
                int row = id >> 3, ch = id & 7;
                uint32_t off = swz((row << 7) + (ch << 4));
                cp16(sa + off, Abase + (size_t)row * K + (cs << 6) + (ch << 3));
                cp16(sbm + off, Bbase + (size_t)row * K + (cs << 6) + (ch << 3));
            }
            CP_COMMIT();
        }
        const char* As = smem + (c % 3) * 32768;
        const char* Bs = As + 16384;
#pragma unroll
        for (int ks = 0; ks < 4; ks++) {
            int kb = ks << 5;
            uint32_t af[4][4];
#pragma unroll
            for (int mi = 0; mi < 4; mi++) {
                int r = wm0 + (mi << 4) + g;
                af[mi][0] = *(const uint32_t*)(As + swz((r << 7) + kb + (q << 2)));
                af[mi][1] = *(const uint32_t*)(As + swz(((r + 8) << 7) + kb + (q << 2)));
                af[mi][2] = *(const uint32_t*)(As + swz((r << 7) + kb + 16 + (q << 2)));
                af[mi][3] = *(const uint32_t*)(As + swz(((r + 8) << 7) + kb + 16 + (q << 2)));
            }
            uint32_t bf[4][2];
#pragma unroll
            for (int ni = 0; ni < 4; ni++) {
                int n = wn0 + (ni << 3) + g;
                bf[ni][0] = *(const uint32_t*)(Bs + swz((n << 7) + kb + (q << 2)));
                bf[ni][1] = *(const uint32_t*)(Bs + swz((n << 7) + kb + 16 + (q << 2)));
            }
#pragma unroll
            for (int mi = 0; mi < 4; mi++)
#pragma unroll
                for (int ni = 0; ni < 4; ni++)
                    mma_f16(acc[mi][ni], af[mi], bf[ni]);
        }
    }

#pragma unroll
    for (int mi = 0; mi < 4; mi++) {
#pragma unroll
        for (int half = 0; half < 2; half++) {
            int row = m0 + wm0 + (mi << 4) + g + half * 8;
            const float* rrow = res ? res + (size_t)row * N : nullptr;
#pragma unroll
            for (int ni = 0; ni < 4; ni++) {
                int col = n0 + wn0 + (ni << 3) + (q << 1);
                float v0 = acc[mi][ni][half * 2 + 0];
                float v1 = acc[mi][ni][half * 2 + 1];
                if (bias) { v0 += bias[col]; v1 += bias[col + 1]; }
                if (relu) { v0 = fmaxf(v0, 0.f); v1 = fmaxf(v1, 0.f); }
                if (rrow) { v0 += rrow[col]; v1 += rrow[col + 1]; }
                if (Ch) {
                    *(uint32_t*)(Ch + (size_t)row * N + col) = packh2(v0, v1);
                } else {
                    float2 o; o.x = v0; o.y = v1;
                    *(float2*)(C + (size_t)row * N + col) = o;
                }
            }
        }
    }
}

// ---------------- fused flash attention --------------------------------------
__global__ __launch_bounds__(128) void flash_attn(
    const __half* __restrict__ qkv, __half* __restrict__ o)
{
    __shared__ __align__(16) __half Qs[64 * 64];
    __shared__ __align__(16) __half Ks[2][64 * 64];
    __shared__ __align__(16) __half Vs[2][64 * 64];

    int it = (int)gridDim.x - 1 - (int)blockIdx.x;   // longest tiles first
    int bh = blockIdx.y;
    int b = bh >> 4, h = bh & 15;
    int tid = threadIdx.x;
    int wid = tid >> 5, lane = tid & 31;
    int g = lane >> 2, q = lane & 3;
    int wr = wid << 4;

    const __half* Qg = qkv + ((size_t)b * TT + (size_t)it * 64) * C3 + h * 64;

#pragma unroll
    for (int p = 0; p < 4; p++) {
        int id = p * 128 + tid;
        int row = id >> 3, ch = id & 7;
        cp16((char*)Qs + swz((row << 7) + (ch << 4)), Qg + (size_t)row * C3 + (ch << 3));
    }
    CP_COMMIT();

    {
        const __half* Kg = qkv + (size_t)b * TT * C3 + CC + h * 64;
        const __half* Vg = qkv + (size_t)b * TT * C3 + 2 * CC + h * 64;
#pragma unroll
        for (int p = 0; p < 4; p++) {
            int id = p * 128 + tid;
            int row = id >> 3, ch = id & 7;
            uint32_t off = swz((row << 7) + (ch << 4));
            cp16((char*)Ks[0] + off, Kg + (size_t)row * C3 + (ch << 3));
            cp16((char*)Vs[0] + off, Vg + (size_t)row * C3 + (ch << 3));
        }
        CP_COMMIT();
    }

    float m0 = -1e30f, m1 = -1e30f;
    float l0 = 0.f, l1 = 0.f;
    float oacc[8][4] = {};

    for (int jt = 0; jt <= it; jt++) {
        int buf = jt & 1;
        if (jt < it) {
            int nb = (jt + 1) & 1;
            const __half* Kg = qkv + ((size_t)b * TT + (size_t)(jt + 1) * 64) * C3 + CC + h * 64;
            const __half* Vg = qkv + ((size_t)b * TT + (size_t)(jt + 1) * 64) * C3 + 2 * CC + h * 64;
#pragma unroll
            for (int p = 0; p < 4; p++) {
                int id = p * 128 + tid;
                int row = id >> 3, ch = id & 7;
                uint32_t off = swz((row << 7) + (ch << 4));
                cp16((char*)Ks[nb] + off, Kg + (size_t)row * C3 + (ch << 3));
                cp16((char*)Vs[nb] + off, Vg + (size_t)row * C3 + (ch << 3));
            }
            CP_COMMIT();
            CP_WAIT(1);
        } else {
            CP_WAIT(0);
        }
        __syncthreads();

        float sacc[8][4] = {};
        const char* Qb = (const char*)Qs;
        const char* Kb = (const char*)Ks[buf];
#pragma unroll
        for (int ks = 0; ks < 4; ks++) {
            int kb = ks << 5;
            uint32_t af[4];
            af[0] = *(const uint32_t*)(Qb + swz(((wr + g) << 7) + kb + (q << 2)));
            af[1] = *(const uint32_t*)(Qb + swz(((wr + g + 8) << 7) + kb + (q << 2)));
            af[2] = *(const uint32_t*)(Qb + swz(((wr + g) << 7) + kb + 16 + (q << 2)));
            af[3] = *(const uint32_t*)(Qb + swz(((wr + g + 8) << 7) + kb + 16 + (q << 2)));
#pragma unroll
            for (int nt = 0; nt < 8; nt++) {
                uint32_t bf[2];
                bf[0] = *(const uint32_t*)(Kb + swz((((nt << 3) + g) << 7) + kb + (q << 2)));
                bf[1] = *(const uint32_t*)(Kb + swz((((nt << 3) + g) << 7) + kb + 16 + (q << 2)));
                mma_f16(sacc[nt], af, bf);
            }
        }

        bool diag = (jt == it);
        float mn0 = -1e30f, mn1 = -1e30f;
#pragma unroll
        for (int nt = 0; nt < 8; nt++) {
#pragma unroll
            for (int j = 0; j < 4; j++) {
                float s = sacc[nt][j] * 0.125f;
                if (diag) {
                    int col = (nt << 3) + (q << 1) + (j & 1);
                    int row = wr + g + ((j >> 1) << 3);
                    if (col > row) s = -1e30f;
                }
                sacc[nt][j] = s;
            }
            mn0 = fmaxf(mn0, fmaxf(sacc[nt][0], sacc[nt][1]));
            mn1 = fmaxf(mn1, fmaxf(sacc[nt][2], sacc[nt][3]));
        }
        mn0 = fmaxf(mn0, __shfl_xor_sync(0xffffffffu, mn0, 1));
        mn0 = fmaxf(mn0, __shfl_xor_sync(0xffffffffu, mn0, 2));
        mn1 = fmaxf(mn1, __shfl_xor_sync(0xffffffffu, mn1, 1));
        mn1 = fmaxf(mn1, __shfl_xor_sync(0xffffffffu, mn1, 2));

        float mnew0 = fmaxf(m0, mn0), mnew1 = fmaxf(m1, mn1);
        float a0 = __expf(m0 - mnew0), a1 = __expf(m1 - mnew1);
        m0 = mnew0; m1 = mnew1;

        float rs0 = 0.f, rs1 = 0.f;
        uint32_t ph[8][2];
#pragma unroll
        for (int nt = 0; nt < 8; nt++) {
            float p0 = __expf(sacc[nt][0] - m0);
            float p1 = __expf(sacc[nt][1] - m0);
            float p2 = __expf(sacc[nt][2] - m1);
            float p3 = __expf(sacc[nt][3] - m1);
            rs0 += p0 + p1; rs1 += p2 + p3;
            ph[nt][0] = packh2(p0, p1);
            ph[nt][1] = packh2(p2, p3);
        }
        rs0 += __shfl_xor_sync(0xffffffffu, rs0, 1);
        rs0 += __shfl_xor_sync(0xffffffffu, rs0, 2);
        rs1 += __shfl_xor_sync(0xffffffffu, rs1, 1);
        rs1 += __shfl_xor_sync(0xffffffffu, rs1, 2);
        l0 = l0 * a0 + rs0;
        l1 = l1 * a1 + rs1;
#pragma unroll
        for (int nt = 0; nt < 8; nt++) {
            oacc[nt][0] *= a0; oacc[nt][1] *= a0;
            oacc[nt][2] *= a1; oacc[nt][3] *= a1;
        }

        uint32_t vbase = smem_u32(Vs[buf]);
        int t = lane >> 3, r = lane & 7;
#pragma unroll
        for (int s = 0; s < 4; s++) {
            uint32_t pa[4] = { ph[2 * s][0], ph[2 * s][1], ph[2 * s + 1][0], ph[2 * s + 1][1] };
#pragma unroll
            for (int ntp = 0; ntp < 4; ntp++) {
                uint32_t b0, b1, b2, b3;
                uint32_t la = vbase + swz((((s << 4) + ((t & 1) << 3) + r) << 7) +
                                          (((ntp << 1) + (t >> 1)) << 4));
                ldsm_x4_t(b0, b1, b2, b3, la);
                uint32_t bA[2] = { b0, b1 }, bB[2] = { b2, b3 };
                mma_f16(oacc[2 * ntp], pa, bA);
                mma_f16(oacc[2 * ntp + 1], pa, bB);
            }
        }
        __syncthreads();
    }

    float i0 = 1.f / l0, i1 = 1.f / l1;
    int rowg = b * TT + it * 64 + wr + g;
    __half* O0 = o + (size_t)rowg * CC + h * 64;
    __half* O1 = o + (size_t)(rowg + 8) * CC + h * 64;
#pragma unroll
    for (int nt = 0; nt < 8; nt++) {
        int col = (nt << 3) + (q << 1);
        *(uint32_t*)(O0 + col) = packh2(oacc[nt][0] * i0, oacc[nt][1] * i0);
        *(uint32_t*)(O1 + col) = packh2(oacc[nt][2] * i1, oacc[nt][3] * i1);
    }
}

// ---------------- loss: split-vocab online logsumexp partials ----------------
__global__ __launch_bounds__(256) void row_loss_part(
    const float* __restrict__ logits, float2* __restrict__ part)
{
    __shared__ float buf[256];
    int row = blockIdx.x, chunk = blockIdx.y;
    const float* lr = logits + (size_t)row * VV + (size_t)chunk * VCH;
    float m = -3.4e38f, s = 0.f;
    // VCH = 12576 = 3144 float4
    for (int j = threadIdx.x; j < (VCH >> 2); j += 256) {
        float4 v = *(const float4*)(lr + (j << 2));
        float vm = fmaxf(fmaxf(v.x, v.y), fmaxf(v.z, v.w));
        if (vm > m) { s *= __expf(m - vm); m = vm; }
        s += __expf(v.x - m) + __expf(v.y - m) + __expf(v.z - m) + __expf(v.w - m);
    }
    float gm = block_reduce_max(m, buf);
    s = block_reduce_sum(s * __expf(m - gm), buf);
    if (threadIdx.x == 0) {
        float2 o; o.x = gm; o.y = s;
        part[(size_t)row * NSPL + chunk] = o;
    }
}

// merge NSPL partials per row + gather target logit (1 thread per row)
__global__ __launch_bounds__(256) void row_loss_merge(
    const float* __restrict__ logits, const float2* __restrict__ part,
    const int* __restrict__ targets, float* __restrict__ rl)
{
    int row = blockIdx.x * 256 + threadIdx.x;
    if (row >= NN) return;
    const float2* pr = part + (size_t)row * NSPL;
    float m = -3.4e38f, s = 0.f;
#pragma unroll
    for (int j = 0; j < NSPL; j++) {
        float2 p = pr[j];
        float nm = fmaxf(m, p.x);
        s = s * __expf(m - nm) + p.y * __expf(p.x - nm);
        m = nm;
    }
    int t = targets[row];
    rl[row] = -(logits[(size_t)row * VV + t] - m - logf(s));
}

__global__ __launch_bounds__(256) void loss_reduce_kernel(
    const float* __restrict__ rl, float* __restrict__ out)
{
    __shared__ float buf[256];
    float s = 0.f;
    for (int i = threadIdx.x; i < NN; i += 256) s += rl[i];
    s = block_reduce_sum(s, buf);
    if (threadIdx.x == 0) out[0] = s * (1.f / NN);
}

// ---------------- host orchestration ----------------------------------------
static inline void run_gemm(const __half* A, const __half* Wt, const float* bias,
                            const float* res, float* C, __half* Ch,
                            int M, int N, int K, int relu)
{
    int grid = (M / 128) * (N / 128);
    mma_gemm_kernel<<<grid, 256, GEMM_SMEM>>>(A, Wt, bias, res, C, Ch, M, N, K, relu);
}

extern "C" void kernel_launch(void* const* d_in, const int* in_sizes, int n_in,
                              void* d_out, int out_size)
{
    const int*   idx     = (const int*)  d_in[0];
    const int*   targets = (const int*)  d_in[1];
    const float* tok     = (const float*)d_in[2];
    const float* pos     = (const float*)d_in[3];
    const float* ln1_g   = (const float*)d_in[4];
    const float* ln1_b   = (const float*)d_in[5];
    const float* Wq      = (const float*)d_in[6];
    const float* Wk      = (const float*)d_in[7];
    const float* Wv      = (const float*)d_in[8];
    const float* Wo      = (const float*)d_in[9];
    const float* bo      = (const float*)d_in[10];
    const float* ln2_g   = (const float*)d_in[11];
    const float* ln2_b   = (const float*)d_in[12];
    const float* W1      = (const float*)d_in[13];
    const float* b1      = (const float*)d_in[14];
    const float* W2      = (const float*)d_in[15];
    const float* b2      = (const float*)d_in[16];
    const float* lnf_g   = (const float*)d_in[17];
    const float* lnf_b   = (const float*)d_in[18];
    const float* Wlm     = (const float*)d_in[19];
    const float* blm     = (const float*)d_in[20];
    (void)in_sizes; (void)n_in;

    cudaFuncSetAttribute(mma_gemm_kernel,
                         cudaFuncAttributeMaxDynamicSharedMemorySize, GEMM_SMEM);

    void* p;
    cudaGetSymbolAddress(&p, g_x);      float*  x    = (float*)p;
    cudaGetSymbolAddress(&p, g_h);      __half* h    = (__half*)p;
    cudaGetSymbolAddress(&p, g_qkv);    __half* qkv  = (__half*)p;
    cudaGetSymbolAddress(&p, g_att);    __half* att  = (__half*)p;
    cudaGetSymbolAddress(&p, g_ffh);    __half* ffh  = (__half*)p;
    cudaGetSymbolAddress(&p, g_rowloss);float*  rl   = (float*)p;
    cudaGetSymbolAddress(&p, g_lsep);   float2* lsep = (float2*)p;
    cudaGetSymbolAddress(&p, g_logits_fb); float* logits_fb = (float*)p;
    cudaGetSymbolAddress(&p, g_WqkvT);  __half* WqkvT = (__half*)p;
    cudaGetSymbolAddress(&p, g_WoT);    __half* WoT  = (__half*)p;
    cudaGetSymbolAddress(&p, g_W1T);    __half* W1T  = (__half*)p;
    cudaGetSymbolAddress(&p, g_W2T);    __half* W2T  = (__half*)p;
    cudaGetSymbolAddress(&p, g_WlmT);   __half* WlmT = (__half*)p;

    const size_t NV = (size_t)NN * VV;
    float* out = (float*)d_out;
    bool big = ((size_t)out_size >= NV);
    float* logits   = big ? out : logits_fb;
    float* loss_dst = ((size_t)out_size > NV) ? out + NV
                    : (big ? rl + NN : out);

    // transpose all weights to fp16 [N,K]; QKV packed as [3C,K] (64x64 tiles)
    transpose_kernel<<<dim3(CC/64, CC/64, LL), 256>>>(Wq, WqkvT + 0 * (size_t)CC * CC,
        CC, CC, (size_t)CC * CC, (size_t)C3 * CC);
    transpose_kernel<<<dim3(CC/64, CC/64, LL), 256>>>(Wk, WqkvT + 1 * (size_t)CC * CC,
        CC, CC, (size_t)CC * CC, (size_t)C3 * CC);
    transpose_kernel<<<dim3(CC/64, CC/64, LL), 256>>>(Wv, WqkvT + 2 * (size_t)CC * CC,
        CC, CC, (size_t)CC * CC, (size_t)C3 * CC);
    transpose_kernel<<<dim3(CC/64, CC/64, LL), 256>>>(Wo, WoT, CC, CC,
        (size_t)CC * CC, (size_t)CC * CC);
    transpose_kernel<<<dim3(FF/64, CC/64, LL), 256>>>(W1, W1T, CC, FF,
        (size_t)CC * FF, (size_t)CC * FF);
    transpose_kernel<<<dim3(CC/64, FF/64, LL), 256>>>(W2, W2T, FF, CC,
        (size_t)FF * CC, (size_t)FF * CC);
    transpose_kernel<<<dim3(VV/64, CC/64, 1),  256>>>(Wlm, WlmT, CC, VV, 0, 0);

    // embedding
    embed_kernel<<<(NN * CC / 4) / 256, 256>>>(idx, tok, pos, x);

    for (int l = 0; l < LL; l++) {
        const size_t oC  = (size_t)l * CC;
        const size_t oCC = (size_t)l * CC * CC;
        const size_t oCF = (size_t)l * CC * FF;
        const size_t oF  = (size_t)l * FF;
        const size_t oQ  = (size_t)l * C3 * CC;

        ln_kernel<<<NN, 256>>>(x, ln1_g + oC, ln1_b + oC, h);
        run_gemm(h, WqkvT + oQ, nullptr, nullptr, nullptr, qkv, NN, C3, CC, 0);

        flash_attn<<<dim3(TT / 64, BB * HH), 128>>>(qkv, att);

        run_gemm(att, WoT + oCC, bo + oC, x, x, nullptr, NN, CC, CC, 0);

        ln_kernel<<<NN, 256>>>(x, ln2_g + oC, ln2_b + oC, h);
        run_gemm(h, W1T + oCF, b1 + oF, nullptr, nullptr, ffh, NN, FF, CC, 1);
        run_gemm(ffh, W2T + oCF, b2 + oC, x, x, nullptr, NN, CC, FF, 0);
    }

    ln_kernel<<<NN, 256>>>(x, lnf_g, lnf_b, h);
    run_gemm(h, WlmT, blm, nullptr, logits, nullptr, NN, VV, CC, 0);

    row_loss_part<<<dim3(NN, NSPL), 256>>>(logits, lsep);
    row_loss_merge<<<NN / 256, 256>>>(logits, lsep, targets, rl);
    loss_reduce_kernel<<<1, 256>>>(rl, loss_dst);
}

// round 16
// speedup vs baseline: 1.0423x; 1.0092x over previous
#include <cuda_runtime.h>
#include <cuda_fp16.h>
#include <cstdint>

// Problem constants
#define BB 4
#define TT 1024
#define CC 1024
#define HH 16
#define HS 64
#define LL 12
#define VV 50304
#define NN (BB*TT)          // 4096 tokens
#define FF (4*CC)           // 4096
#define C3 (3*CC)           // 3072

// ---------------- scratch (device globals; no allocation allowed) -----------
__device__ float  g_x[NN*CC];
__device__ __half g_h[NN*CC];
__device__ __half g_qkv[(size_t)NN*C3];
__device__ __half g_att[NN*CC];
__device__ __half g_ffh[(size_t)NN*FF];
__device__ float  g_rowloss[NN + 4];
__device__ float  g_logits_fb[(size_t)NN*VV];    // fallback if d_out too small
// transposed weights [N,K] (fp16)
__device__ __half g_WqkvT[(size_t)LL*C3*CC];     // rows: [Wq; Wk; Wv]
__device__ __half g_WoT[(size_t)LL*CC*CC];
__device__ __half g_W1T[(size_t)LL*CC*FF];
__device__ __half g_W2T[(size_t)LL*FF*CC];
__device__ __half g_WlmT[(size_t)CC*VV];

// ---------------- helpers ----------------------------------------------------
__device__ __forceinline__ uint32_t smem_u32(const void* p) {
    uint32_t a;
    asm("{ .reg .u64 t; cvta.to.shared.u64 t, %1; cvt.u32.u64 %0, t; }" : "=r"(a) : "l"(p));
    return a;
}
__device__ __forceinline__ uint32_t swz(uint32_t b) { return b ^ ((b >> 3) & 0x70); }

__device__ __forceinline__ void cp16(void* s, const void* g) {
    uint32_t sa = smem_u32(s);
    asm volatile("cp.async.cg.shared.global [%0], [%1], 16;" :: "r"(sa), "l"(g));
}
#define CP_COMMIT() asm volatile("cp.async.commit_group;" ::: "memory")
#define CP_WAIT(n)  asm volatile("cp.async.wait_group %0;" :: "n"(n) : "memory")

__device__ __forceinline__ void mma_f16(float* d, const uint32_t* a, const uint32_t* b) {
    asm volatile(
        "mma.sync.aligned.m16n8k16.row.col.f32.f16.f16.f32 "
        "{%0,%1,%2,%3}, {%4,%5,%6,%7}, {%8,%9}, {%0,%1,%2,%3};"
        : "+f"(d[0]), "+f"(d[1]), "+f"(d[2]), "+f"(d[3])
        : "r"(a[0]), "r"(a[1]), "r"(a[2]), "r"(a[3]), "r"(b[0]), "r"(b[1]));
}
__device__ __forceinline__ void ldsm_x4_t(uint32_t& r0, uint32_t& r1,
                                          uint32_t& r2, uint32_t& r3, uint32_t addr) {
    asm volatile("ldmatrix.sync.aligned.m8n8.x4.trans.shared.b16 {%0,%1,%2,%3}, [%4];"
        : "=r"(r0), "=r"(r1), "=r"(r2), "=r"(r3) : "r"(addr));
}
__device__ __forceinline__ uint32_t packh2(float a, float b) {
    __half2 h = __floats2half2_rn(a, b);
    return *(uint32_t*)&h;
}

// ---------------- reductions ------------------------------------------------
__device__ __forceinline__ float block_reduce_sum(float v, float* buf) {
    int tid = threadIdx.x;
    buf[tid] = v; __syncthreads();
    for (int s = 128; s > 0; s >>= 1) {
        if (tid < s) buf[tid] += buf[tid + s];
        __syncthreads();
    }
    float r = buf[0]; __syncthreads();
    return r;
}
__device__ __forceinline__ float block_reduce_max(float v, float* buf) {
    int tid = threadIdx.x;
    buf[tid] = v; __syncthreads();
    for (int s = 128; s > 0; s >>= 1) {
        if (tid < s) buf[tid] = fmaxf(buf[tid], buf[tid + s]);
        __syncthreads();
    }
    float r = buf[0]; __syncthreads();
    return r;
}

// ---------------- transpose: dst[N,K] = half(src[K,N]), 64x64 tiles ----------
__global__ __launch_bounds__(256) void transpose_kernel(
    const float* __restrict__ src, __half* __restrict__ dst, int K, int N,
    size_t src_zstride, size_t dst_zstride)
{
    __shared__ float t[64][65];
    const float* s = src + (size_t)blockIdx.z * src_zstride;
    __half* d = dst + (size_t)blockIdx.z * dst_zstride;
    int n0 = blockIdx.x << 6, k0 = blockIdx.y << 6;
    int tid = threadIdx.x;
    int r = tid >> 4, c4 = (tid & 15) << 2;
#pragma unroll
    for (int p = 0; p < 4; p++) {
        float4 v = *(const float4*)(s + (size_t)(k0 + r + p * 16) * N + n0 + c4);
        t[r + p * 16][c4 + 0] = v.x; t[r + p * 16][c4 + 1] = v.y;
        t[r + p * 16][c4 + 2] = v.z; t[r + p * 16][c4 + 3] = v.w;
    }
    __syncthreads();
    int lane = tid & 31, w = tid >> 5;
#pragma unroll
    for (int p = 0; p < 8; p++) {
        int n = w + (p << 3);
        int k = lane << 1;
        *(uint32_t*)(d + (size_t)(n0 + n) * K + k0 + k) =
            packh2(t[k][n], t[k + 1][n]);
    }
}

// ---------------- embedding (float4) -----------------------------------------
__global__ __launch_bounds__(256) void embed_kernel(
    const int* __restrict__ idx, const float* __restrict__ tok,
    const float* __restrict__ pos, float* __restrict__ x)
{
    size_t i4 = (size_t)blockIdx.x * 256 + threadIdx.x;   // over NN*CC/4
    int n = (int)(i4 >> 8);
    int c = (int)(i4 & 255) << 2;
    int t = n & (TT - 1);
    float4 tv = *(const float4*)(tok + (size_t)idx[n] * CC + c);
    float4 pv = *(const float4*)(pos + (size_t)t * CC + c);
    float4 o; o.x = tv.x + pv.x; o.y = tv.y + pv.y; o.z = tv.z + pv.z; o.w = tv.w + pv.w;
    *(float4*)(x + (size_t)n * CC + c) = o;
}

// ---------------- layernorm (warp-shfl reduce, 1 syncthreads) ----------------
__global__ __launch_bounds__(256) void ln_kernel(
    const float* __restrict__ x, const float* __restrict__ g,
    const float* __restrict__ b, __half* __restrict__ out)
{
    __shared__ float ws[8], wss[8];
    int tid = threadIdx.x;
    int row = blockIdx.x;
    int c = tid << 2;
    const float* xr = x + (size_t)row * CC;
    float4 v = *(const float4*)(xr + c);
    float s  = v.x + v.y + v.z + v.w;
    float ss = v.x * v.x + v.y * v.y + v.z * v.z + v.w * v.w;
#pragma unroll
    for (int o = 16; o > 0; o >>= 1) {
        s  += __shfl_down_sync(0xffffffffu, s, o);
        ss += __shfl_down_sync(0xffffffffu, ss, o);
    }
    if ((tid & 31) == 0) { ws[tid >> 5] = s; wss[tid >> 5] = ss; }
    __syncthreads();
    float S = 0.f, SS = 0.f;
#pragma unroll
    for (int i = 0; i < 8; i++) { S += ws[i]; SS += wss[i]; }
    float mu  = S * (1.f / CC);
    float inv = rsqrtf(SS * (1.f / CC) - mu * mu + 1e-5f);
    float4 gv = *(const float4*)(g + c);
    float4 bv = *(const float4*)(b + c);
    uint2 o;
    o.x = packh2((v.x - mu) * inv * gv.x + bv.x, (v.y - mu) * inv * gv.y + bv.y);
    o.y = packh2((v.z - mu) * inv * gv.z + bv.z, (v.w - mu) * inv * gv.w + bv.w);
    *(uint2*)(out + (size_t)row * CC + c) = o;
}

// ---------------- mma.sync fp16 GEMM: C = A[M,K] @ Bt[N,K]^T -----------------
// BM=128, BN=128, BK=64, 256 threads (8 warps, 2x4), 3-stage cp.async pipeline.
// Proven R8/R10 configuration — scalar swizzled LDS fragments. Do NOT cap regs,
// do NOT touch the epilogue while acc is live, do NOT fuse reductions here
// (R4/R12/R14 lessons — this kernel is at its register ceiling).
#define GEMM_SMEM (3*32768)
#define GW 16
__global__ __launch_bounds__(256) void mma_gemm_kernel(
    const __half* __restrict__ A, const __half* __restrict__ Bt,
    const float* __restrict__ bias, const float* __restrict__ res,
    float* __restrict__ C, __half* __restrict__ Ch,
    int M, int N, int K, int relu)
{
    extern __shared__ char smem[];
    int tid = threadIdx.x;
    int wid = tid >> 5, lane = tid & 31;
    int g = lane >> 2, q = lane & 3;
    int wm0 = (wid >> 2) << 6;
    int wn0 = (wid & 3) << 5;

    int Mb = M >> 7, Nb = N >> 7;
    int bid = blockIdx.x;
    int group = bid / (Mb * GW);
    int rem = bid - group * Mb * GW;
    int gw = Nb - group * GW; if (gw > GW) gw = GW;
    int n_blk = group * GW + rem % gw;
    int m_blk = rem / gw;
    int m0 = m_blk << 7, n0 = n_blk << 7;

    const __half* Abase = A + (size_t)m0 * K;
    const __half* Bbase = Bt + (size_t)n0 * K;
    int Kc = K >> 6;

    float acc[4][4][4] = {};

#pragma unroll
    for (int c = 0; c < 2; c++) {
        char* sa = smem + c * 32768;
        char* sbm = sa + 16384;
#pragma unroll
        for (int p = 0; p < 4; p++) {
            int id = p * 256 + tid;
            int row = id >> 3, ch = id & 7;
            uint32_t off = swz((row << 7) + (ch << 4));
            cp16(sa + off, Abase + (size_t)row * K + (c << 6) + (ch << 3));
            cp16(sbm + off, Bbase + (size_t)row * K + (c << 6) + (ch << 3));
        }
        CP_COMMIT();
    }

    for (int c = 0; c < Kc; c++) {
        if (c + 2 < Kc) { CP_WAIT(1); } else { CP_WAIT(0); }
        __syncthreads();
        if (c + 2 < Kc) {
            int cs = c + 2;
            char* sa = smem + (cs % 3) * 32768;
            char* sbm = sa + 16384;
#pragma unroll
            for (int p = 0; p < 4; p++) {
                int id = p * 256 + tid;
                int row = id >> 3, ch = id & 7;
                uint32_t off = swz((row << 7) + (ch << 4));
                cp16(sa + off, Abase + (size_t)row * K + (cs << 6) + (ch << 3));
                cp16(sbm + off, Bbase + (size_t)row * K + (cs << 6) + (ch << 3));
            }
            CP_COMMIT();
        }
        const char* As = smem + (c % 3) * 32768;
        const char* Bs = As + 16384;
#pragma unroll
        for (int ks = 0; ks < 4; ks++) {
            int kb = ks << 5;
            uint32_t af[4][4];
#pragma unroll
            for (int mi = 0; mi < 4; mi++) {
                int r = wm0 + (mi << 4) + g;
                af[mi][0] = *(const uint32_t*)(As + swz((r << 7) + kb + (q << 2)));
                af[mi][1] = *(const uint32_t*)(As + swz(((r + 8) << 7) + kb + (q << 2)));
                af[mi][2] = *(const uint32_t*)(As + swz((r << 7) + kb + 16 + (q << 2)));
                af[mi][3] = *(const uint32_t*)(As + swz(((r + 8) << 7) + kb + 16 + (q << 2)));
            }
            uint32_t bf[4][2];
#pragma unroll
            for (int ni = 0; ni < 4; ni++) {
                int n = wn0 + (ni << 3) + g;
                bf[ni][0] = *(const uint32_t*)(Bs + swz((n << 7) + kb + (q << 2)));
                bf[ni][1] = *(const uint32_t*)(Bs + swz((n << 7) + kb + 16 + (q << 2)));
            }
#pragma unroll
            for (int mi = 0; mi < 4; mi++)
#pragma unroll
                for (int ni = 0; ni < 4; ni++)
                    mma_f16(acc[mi][ni], af[mi], bf[ni]);
        }
    }

#pragma unroll
    for (int mi = 0; mi < 4; mi++) {
#pragma unroll
        for (int half = 0; half < 2; half++) {
            int row = m0 + wm0 + (mi << 4) + g + half * 8;
            const float* rrow = res ? res + (size_t)row * N : nullptr;
#pragma unroll
            for (int ni = 0; ni < 4; ni++) {
                int col = n0 + wn0 + (ni << 3) + (q << 1);
                float v0 = acc[mi][ni][half * 2 + 0];
                float v1 = acc[mi][ni][half * 2 + 1];
                if (bias) { v0 += bias[col]; v1 += bias[col + 1]; }
                if (relu) { v0 = fmaxf(v0, 0.f); v1 = fmaxf(v1, 0.f); }
                if (rrow) { v0 += rrow[col]; v1 += rrow[col + 1]; }
                if (Ch) {
                    *(uint32_t*)(Ch + (size_t)row * N + col) = packh2(v0, v1);
                } else {
                    float2 o; o.x = v0; o.y = v1;
                    *(float2*)(C + (size_t)row * N + col) = o;
                }
            }
        }
    }
}

// ---------------- fused flash attention --------------------------------------
__global__ __launch_bounds__(128) void flash_attn(
    const __half* __restrict__ qkv, __half* __restrict__ o)
{
    __shared__ __align__(16) __half Qs[64 * 64];
    __shared__ __align__(16) __half Ks[2][64 * 64];
    __shared__ __align__(16) __half Vs[2][64 * 64];

    int it = (int)gridDim.x - 1 - (int)blockIdx.x;   // longest tiles first
    int bh = blockIdx.y;
    int b = bh >> 4, h = bh & 15;
    int tid = threadIdx.x;
    int wid = tid >> 5, lane = tid & 31;
    int g = lane >> 2, q = lane & 3;
    int wr = wid << 4;

    const __half* Qg = qkv + ((size_t)b * TT + (size_t)it * 64) * C3 + h * 64;

#pragma unroll
    for (int p = 0; p < 4; p++) {
        int id = p * 128 + tid;
        int row = id >> 3, ch = id & 7;
        cp16((char*)Qs + swz((row << 7) + (ch << 4)), Qg + (size_t)row * C3 + (ch << 3));
    }
    CP_COMMIT();

    {
        const __half* Kg = qkv + (size_t)b * TT * C3 + CC + h * 64;
        const __half* Vg = qkv + (size_t)b * TT * C3 + 2 * CC + h * 64;
#pragma unroll
        for (int p = 0; p < 4; p++) {
            int id = p * 128 + tid;
            int row = id >> 3, ch = id & 7;
            uint32_t off = swz((row << 7) + (ch << 4));
            cp16((char*)Ks[0] + off, Kg + (size_t)row * C3 + (ch << 3));
            cp16((char*)Vs[0] + off, Vg + (size_t)row * C3 + (ch << 3));
        }
        CP_COMMIT();
    }

    float m0 = -1e30f, m1 = -1e30f;
    float l0 = 0.f, l1 = 0.f;
    float oacc[8][4] = {};

    for (int jt = 0; jt <= it; jt++) {
        int buf = jt & 1;
        if (jt < it) {
            int nb = (jt + 1) & 1;
            const __half* Kg = qkv + ((size_t)b * TT + (size_t)(jt + 1) * 64) * C3 + CC + h * 64;
            const __half* Vg = qkv + ((size_t)b * TT + (size_t)(jt + 1) * 64) * C3 + 2 * CC + h * 64;
#pragma unroll
            for (int p = 0; p < 4; p++) {
                int id = p * 128 + tid;
                int row = id >> 3, ch = id & 7;
                uint32_t off = swz((row << 7) + (ch << 4));
                cp16((char*)Ks[nb] + off, Kg + (size_t)row * C3 + (ch << 3));
                cp16((char*)Vs[nb] + off, Vg + (size_t)row * C3 + (ch << 3));
            }
            CP_COMMIT();
            CP_WAIT(1);
        } else {
            CP_WAIT(0);
        }
        __syncthreads();

        float sacc[8][4] = {};
        const char* Qb = (const char*)Qs;
        const char* Kb = (const char*)Ks[buf];
#pragma unroll
        for (int ks = 0; ks < 4; ks++) {
            int kb = ks << 5;
            uint32_t af[4];
            af[0] = *(const uint32_t*)(Qb + swz(((wr + g) << 7) + kb + (q << 2)));
            af[1] = *(const uint32_t*)(Qb + swz(((wr + g + 8) << 7) + kb + (q << 2)));
            af[2] = *(const uint32_t*)(Qb + swz(((wr + g) << 7) + kb + 16 + (q << 2)));
            af[3] = *(const uint32_t*)(Qb + swz(((wr + g + 8) << 7) + kb + 16 + (q << 2)));
#pragma unroll
            for (int nt = 0; nt < 8; nt++) {
                uint32_t bf[2];
                bf[0] = *(const uint32_t*)(Kb + swz((((nt << 3) + g) << 7) + kb + (q << 2)));
                bf[1] = *(const uint32_t*)(Kb + swz((((nt << 3) + g) << 7) + kb + 16 + (q << 2)));
                mma_f16(sacc[nt], af, bf);
            }
        }

        bool diag = (jt == it);
        float mn0 = -1e30f, mn1 = -1e30f;
#pragma unroll
        for (int nt = 0; nt < 8; nt++) {
#pragma unroll
            for (int j = 0; j < 4; j++) {
                float s = sacc[nt][j] * 0.125f;
                if (diag) {
                    int col = (nt << 3) + (q << 1) + (j & 1);
                    int row = wr + g + ((j >> 1) << 3);
                    if (col > row) s = -1e30f;
                }
                sacc[nt][j] = s;
            }
            mn0 = fmaxf(mn0, fmaxf(sacc[nt][0], sacc[nt][1]));
            mn1 = fmaxf(mn1, fmaxf(sacc[nt][2], sacc[nt][3]));
        }
        mn0 = fmaxf(mn0, __shfl_xor_sync(0xffffffffu, mn0, 1));
        mn0 = fmaxf(mn0, __shfl_xor_sync(0xffffffffu, mn0, 2));
        mn1 = fmaxf(mn1, __shfl_xor_sync(0xffffffffu, mn1, 1));
        mn1 = fmaxf(mn1, __shfl_xor_sync(0xffffffffu, mn1, 2));

        float mnew0 = fmaxf(m0, mn0), mnew1 = fmaxf(m1, mn1);
        float a0 = __expf(m0 - mnew0), a1 = __expf(m1 - mnew1);
        m0 = mnew0; m1 = mnew1;

        float rs0 = 0.f, rs1 = 0.f;
        uint32_t ph[8][2];
#pragma unroll
        for (int nt = 0; nt < 8; nt++) {
            float p0 = __expf(sacc[nt][0] - m0);
            float p1 = __expf(sacc[nt][1] - m0);
            float p2 = __expf(sacc[nt][2] - m1);
            float p3 = __expf(sacc[nt][3] - m1);
            rs0 += p0 + p1; rs1 += p2 + p3;
            ph[nt][0] = packh2(p0, p1);
            ph[nt][1] = packh2(p2, p3);
        }
        rs0 += __shfl_xor_sync(0xffffffffu, rs0, 1);
        rs0 += __shfl_xor_sync(0xffffffffu, rs0, 2);
        rs1 += __shfl_xor_sync(0xffffffffu, rs1, 1);
        rs1 += __shfl_xor_sync(0xffffffffu, rs1, 2);
        l0 = l0 * a0 + rs0;
        l1 = l1 * a1 + rs1;
#pragma unroll
        for (int nt = 0; nt < 8; nt++) {
            oacc[nt][0] *= a0; oacc[nt][1] *= a0;
            oacc[nt][2] *= a1; oacc[nt][3] *= a1;
        }

        uint32_t vbase = smem_u32(Vs[buf]);
        int t = lane >> 3, r = lane & 7;
#pragma unroll
        for (int s = 0; s < 4; s++) {
            uint32_t pa[4] = { ph[2 * s][0], ph[2 * s][1], ph[2 * s + 1][0], ph[2 * s + 1][1] };
#pragma unroll
            for (int ntp = 0; ntp < 4; ntp++) {
                uint32_t b0, b1, b2, b3;
                uint32_t la = vbase + swz((((s << 4) + ((t & 1) << 3) + r) << 7) +
                                          (((ntp << 1) + (t >> 1)) << 4));
                ldsm_x4_t(b0, b1, b2, b3, la);
                uint32_t bA[2] = { b0, b1 }, bB[2] = { b2, b3 };
                mma_f16(oacc[2 * ntp], pa, bA);
                mma_f16(oacc[2 * ntp + 1], pa, bB);
            }
        }
        __syncthreads();
    }

    float i0 = 1.f / l0, i1 = 1.f / l1;
    int rowg = b * TT + it * 64 + wr + g;
    __half* O0 = o + (size_t)rowg * CC + h * 64;
    __half* O1 = o + (size_t)(rowg + 8) * CC + h * 64;
#pragma unroll
    for (int nt = 0; nt < 8; nt++) {
        int col = (nt << 3) + (q << 1);
        *(uint32_t*)(O0 + col) = packh2(oacc[nt][0] * i0, oacc[nt][1] * i0);
        *(uint32_t*)(O1 + col) = packh2(oacc[nt][2] * i1, oacc[nt][3] * i1);
    }
}

// ---------------- loss: single-pass online logsumexp (R10 proven) ------------
__global__ __launch_bounds__(256) void row_loss_kernel(
    const float* __restrict__ logits, const int* __restrict__ targets,
    float* __restrict__ rl)
{
    __shared__ float buf[256];
    int row = blockIdx.x;
    const float* lr = logits + (size_t)row * VV;
    float m = -3.4e38f, s = 0.f;
    // VV = 50304 = 12576 float4
    for (int j = threadIdx.x; j < 12576; j += 256) {
        float4 v = *(const float4*)(lr + (j << 2));
        float vm = fmaxf(fmaxf(v.x, v.y), fmaxf(v.z, v.w));
        if (vm > m) { s *= __expf(m - vm); m = vm; }
        s += __expf(v.x - m) + __expf(v.y - m) + __expf(v.z - m) + __expf(v.w - m);
    }
    float gm = block_reduce_max(m, buf);
    s = block_reduce_sum(s * __expf(m - gm), buf);
    if (threadIdx.x == 0) {
        int t = targets[row];
        rl[row] = -(lr[t] - gm - logf(s));
    }
}

__global__ __launch_bounds__(256) void loss_reduce_kernel(
    const float* __restrict__ rl, float* __restrict__ out)
{
    __shared__ float buf[256];
    float s = 0.f;
    for (int i = threadIdx.x; i < NN; i += 256) s += rl[i];
    s = block_reduce_sum(s, buf);
    if (threadIdx.x == 0) out[0] = s * (1.f / NN);
}

// ---------------- host orchestration ----------------------------------------
static inline void run_gemm(const __half* A, const __half* Wt, const float* bias,
                            const float* res, float* C, __half* Ch,
                            int M, int N, int K, int relu)
{
    int grid = (M / 128) * (N / 128);
    mma_gemm_kernel<<<grid, 256, GEMM_SMEM>>>(A, Wt, bias, res, C, Ch, M, N, K, relu);
}

extern "C" void kernel_launch(void* const* d_in, const int* in_sizes, int n_in,
                              void* d_out, int out_size)
{
    const int*   idx     = (const int*)  d_in[0];
    const int*   targets = (const int*)  d_in[1];
    const float* tok     = (const float*)d_in[2];
    const float* pos     = (const float*)d_in[3];
    const float* ln1_g   = (const float*)d_in[4];
    const float* ln1_b   = (const float*)d_in[5];
    const float* Wq      = (const float*)d_in[6];
    const float* Wk      = (const float*)d_in[7];
    const float* Wv      = (const float*)d_in[8];
    const float* Wo      = (const float*)d_in[9];
    const float* bo      = (const float*)d_in[10];
    const float* ln2_g   = (const float*)d_in[11];
    const float* ln2_b   = (const float*)d_in[12];
    const float* W1      = (const float*)d_in[13];
    const float* b1      = (const float*)d_in[14];
    const float* W2      = (const float*)d_in[15];
    const float* b2      = (const float*)d_in[16];
    const float* lnf_g   = (const float*)d_in[17];
    const float* lnf_b   = (const float*)d_in[18];
    const float* Wlm     = (const float*)d_in[19];
    const float* blm     = (const float*)d_in[20];
    (void)in_sizes; (void)n_in;

    cudaFuncSetAttribute(mma_gemm_kernel,
                         cudaFuncAttributeMaxDynamicSharedMemorySize, GEMM_SMEM);

    void* p;
    cudaGetSymbolAddress(&p, g_x);      float*  x    = (float*)p;
    cudaGetSymbolAddress(&p, g_h);      __half* h    = (__half*)p;
    cudaGetSymbolAddress(&p, g_qkv);    __half* qkv  = (__half*)p;
    cudaGetSymbolAddress(&p, g_att);    __half* att  = (__half*)p;
    cudaGetSymbolAddress(&p, g_ffh);    __half* ffh  = (__half*)p;
    cudaGetSymbolAddress(&p, g_rowloss);float*  rl   = (float*)p;
    cudaGetSymbolAddress(&p, g_logits_fb); float* logits_fb = (float*)p;
    cudaGetSymbolAddress(&p, g_WqkvT);  __half* WqkvT = (__half*)p;
    cudaGetSymbolAddress(&p, g_WoT);    __half* WoT  = (__half*)p;
    cudaGetSymbolAddress(&p, g_W1T);    __half* W1T  = (__half*)p;
    cudaGetSymbolAddress(&p, g_W2T);    __half* W2T  = (__half*)p;
    cudaGetSymbolAddress(&p, g_WlmT);   __half* WlmT = (__half*)p;

    const size_t NV = (size_t)NN * VV;
    float* out = (float*)d_out;
    bool big = ((size_t)out_size >= NV);
    float* logits   = big ? out : logits_fb;
    float* loss_dst = ((size_t)out_size > NV) ? out + NV
                    : (big ? rl + NN : out);

    // ---- fork weight transposes onto a side stream (overlap with compute) ---
    // Created per call (only 2 calls total: correctness + capture). Not
    // destroyed here: destroying a capture-joined stream before the harness
    // ends capture would invalidate the capture.
    cudaStream_t s2;
    cudaStreamCreateWithFlags(&s2, cudaStreamNonBlocking);
    cudaEvent_t eF, eQKV, eWo, eW1, eW2, eWlm;
    cudaEventCreateWithFlags(&eF,   cudaEventDisableTiming);
    cudaEventCreateWithFlags(&eQKV, cudaEventDisableTiming);
    cudaEventCreateWithFlags(&eWo,  cudaEventDisableTiming);
    cudaEventCreateWithFlags(&eW1,  cudaEventDisableTiming);
    cudaEventCreateWithFlags(&eW2,  cudaEventDisableTiming);
    cudaEventCreateWithFlags(&eWlm, cudaEventDisableTiming);

    cudaEventRecord(eF, 0);
    cudaStreamWaitEvent(s2, eF, 0);

    transpose_kernel<<<dim3(CC/64, CC/64, LL), 256, 0, s2>>>(Wq,
        WqkvT + 0 * (size_t)CC * CC, CC, CC, (size_t)CC * CC, (size_t)C3 * CC);
    transpose_kernel<<<dim3(CC/64, CC/64, LL), 256, 0, s2>>>(Wk,
        WqkvT + 1 * (size_t)CC * CC, CC, CC, (size_t)CC * CC, (size_t)C3 * CC);
    transpose_kernel<<<dim3(CC/64, CC/64, LL), 256, 0, s2>>>(Wv,
        WqkvT + 2 * (size_t)CC * CC, CC, CC, (size_t)CC * CC, (size_t)C3 * CC);
    cudaEventRecord(eQKV, s2);
    transpose_kernel<<<dim3(CC/64, CC/64, LL), 256, 0, s2>>>(Wo, WoT, CC, CC,
        (size_t)CC * CC, (size_t)CC * CC);
    cudaEventRecord(eWo, s2);
    transpose_kernel<<<dim3(FF/64, CC/64, LL), 256, 0, s2>>>(W1, W1T, CC, FF,
        (size_t)CC * FF, (size_t)CC * FF);
    cudaEventRecord(eW1, s2);
    transpose_kernel<<<dim3(CC/64, FF/64, LL), 256, 0, s2>>>(W2, W2T, FF, CC,
        (size_t)FF * CC, (size_t)FF * CC);
    cudaEventRecord(eW2, s2);
    transpose_kernel<<<dim3(VV/64, CC/64, 1),  256, 0, s2>>>(Wlm, WlmT, CC, VV, 0, 0);
    cudaEventRecord(eWlm, s2);

    // ---- main stream: forward pass, waiting on weights just before use ------
    embed_kernel<<<(NN * CC / 4) / 256, 256>>>(idx, tok, pos, x);

    for (int l = 0; l < LL; l++) {
        const size_t oC  = (size_t)l * CC;
        const size_t oCC = (size_t)l * CC * CC;
        const size_t oCF = (size_t)l * CC * FF;
        const size_t oF  = (size_t)l * FF;
        const size_t oQ  = (size_t)l * C3 * CC;

        ln_kernel<<<NN, 256>>>(x, ln1_g + oC, ln1_b + oC, h);
        if (l == 0) cudaStreamWaitEvent(0, eQKV, 0);
        run_gemm(h, WqkvT + oQ, nullptr, nullptr, nullptr, qkv, NN, C3, CC, 0);

        flash_attn<<<dim3(TT / 64, BB * HH), 128>>>(qkv, att);

        if (l == 0) cudaStreamWaitEvent(0, eWo, 0);
        run_gemm(att, WoT + oCC, bo + oC, x, x, nullptr, NN, CC, CC, 0);

        ln_kernel<<<NN, 256>>>(x, ln2_g + oC, ln2_b + oC, h);
        if (l == 0) cudaStreamWaitEvent(0, eW1, 0);
        run_gemm(h, W1T + oCF, b1 + oF, nullptr, nullptr, ffh, NN, FF, CC, 1);
        if (l == 0) cudaStreamWaitEvent(0, eW2, 0);
        run_gemm(ffh, W2T + oCF, b2 + oC, x, x, nullptr, NN, CC, FF, 0);
    }

    ln_kernel<<<NN, 256>>>(x, lnf_g, lnf_b, h);
    cudaStreamWaitEvent(0, eWlm, 0);
    run_gemm(h, WlmT, blm, nullptr, logits, nullptr, NN, VV, CC, 0);

    row_loss_kernel<<<NN, 256>>>(logits, targets, rl);
    loss_reduce_kernel<<<1, 256>>>(rl, loss_dst);
}